// round 14
// baseline (speedup 1.0000x reference)
#include <cuda_runtime.h>
#include <cstdint>
#include <math.h>

typedef unsigned long long ull;

static constexpr int B_ROWS = 262144;
static constexpr int L_STEPS = 20;
static constexpr int TPB = 32;                               // one warp per CTA
static constexpr int ROWS_PER_CTA = 2 * TPB;                 // 64
static constexpr int GRID = B_ROWS / ROWS_PER_CTA;           // 4096

// ---- constant memory: all broadcast operands (warp-uniform reads -> const port) ----
__constant__ float cWdr[2500];   // Wdrift [50,50] row-major (even rows read here)
__constant__ float cBdr[50];
__constant__ float cBd[50];
__constant__ float cB1[100];
__constant__ float cW2[100];
__constant__ float cWfc[100];
__constant__ float cB2[1];
__constant__ float cBfc[2];

// ---- shared memory layout (floats) ----
// sWdrOdd [25*52] @ 0      (1300)   odd Wdrift rows, stride 52 (16B-aligned rows)
// sBuf    [6400]  @ 1300   double noise buffer: buf0 [0,3200), buf1 [3200,6400)
//   phase-1 aliases (sequential): sWd[4800] then sW1[5200]
static constexpr int OFF_WDRODD = 0;
static constexpr int OFF_BUF    = 1300;                      // 1300*4=5200, 16B aligned
static constexpr int SLICE      = 3200;                      // floats per buffer (64 rows)
static constexpr int SMEM_FLOATS = OFF_BUF + 2 * SLICE;      // 7700
static constexpr int SMEM_BYTES  = SMEM_FLOATS * 4;          // 30800 -> 7 CTAs/SM

// ---- packed f32x2 helpers (Blackwell 2x-fp32 path; PTX-only) ----
static __device__ __forceinline__ ull ffma2(ull a, ull b, ull c) {
    ull d;
    asm("fma.rn.f32x2 %0, %1, %2, %3;" : "=l"(d) : "l"(a), "l"(b), "l"(c));
    return d;
}
static __device__ __forceinline__ ull pack2(float lo, float hi) {
    ull r;
    asm("mov.b64 %0, {%1, %2};" : "=l"(r) : "f"(lo), "f"(hi));
    return r;
}
static __device__ __forceinline__ void unpack2(ull v, float& lo, float& hi) {
    asm("mov.b64 {%0, %1}, %2;" : "=f"(lo), "=f"(hi) : "l"(v));
}

static __device__ __forceinline__ unsigned smem_u32(const void* p) {
    return (unsigned)__cvta_generic_to_shared(p);
}
static __device__ __forceinline__ void cp16(void* sdst, const void* gsrc) {
    asm volatile("cp.async.cg.shared.global [%0], [%1], 16;"
                 :: "r"(smem_u32(sdst)), "l"(gsrc) : "memory");
}

// Prologue dot for one row, chunked partial sums (bounded register pressure).
// Wd staged in SMEM, rows padded to 96 floats (zero tail).
static __device__ __forceinline__ void prologue_row(const float* __restrict__ xrow,
                                                    const float* __restrict__ sWd,
                                                    ull* __restrict__ out2) {
#pragma unroll
    for (int p = 0; p < 25; ++p) out2[p] = pack2(cBd[2 * p], cBd[2 * p + 1]);

    for (int c = 0; c < 3; ++c) {
        ull xv[16];
        const ull* xr = (const ull*)xrow + c * 16;
        if (c < 2) {
#pragma unroll
            for (int t = 0; t < 16; ++t) xv[t] = xr[t];
        } else {
#pragma unroll
            for (int t = 0; t < 13; ++t) xv[t] = xr[t];
            xv[13] = 0ull; xv[14] = 0ull; xv[15] = 0ull;   // Wd cols 90..95 are 0
        }
#pragma unroll 5
        for (int p = 0; p < 25; ++p) {
            const ulonglong2* w0 = (const ulonglong2*)(sWd + (2 * p) * 96 + c * 32);
            const ulonglong2* w1 = (const ulonglong2*)(sWd + (2 * p + 1) * 96 + c * 32);
            ull a0 = 0ull, a1 = 0ull;
#pragma unroll
            for (int q = 0; q < 8; ++q) {
                ulonglong2 wa = w0[q];
                a0 = ffma2(wa.x, xv[2 * q],     a0);
                a0 = ffma2(wa.y, xv[2 * q + 1], a0);
                ulonglong2 wb = w1[q];
                a1 = ffma2(wb.x, xv[2 * q],     a1);
                a1 = ffma2(wb.y, xv[2 * q + 1], a1);
            }
            float l0, h0, l1, h1, o0, o1;
            unpack2(a0, l0, h0);
            unpack2(a1, l1, h1);
            unpack2(out2[p], o0, o1);
            out2[p] = pack2(o0 + l0 + h0, o1 + l1 + h1);
        }
    }
}

__global__ void __launch_bounds__(TPB, 7)   // 7 single-warp CTAs/SM
sdenet_kernel(const float* __restrict__ x,      // [B,90]
              const float* __restrict__ Wd,     // [50,90]
              const float* __restrict__ bd,     // [50]
              const float* __restrict__ Wdrift, // [50,50]
              const float* __restrict__ bdrift, // [50]
              const float* __restrict__ W1,     // [100,50]
              const float* __restrict__ b1,     // [100]
              const float* __restrict__ W2,     // [1,100]
              const float* __restrict__ b2,     // [1]
              const float* __restrict__ Wfc,    // [2,50]
              const float* __restrict__ bfc,    // [2]
              const float* __restrict__ noise,  // [L,B,50]
              float* __restrict__ out)          // [2*B] = mean(B) ++ sigma(B)
{
    extern __shared__ float smem[];
    float* sWdrOdd = smem + OFF_WDRODD;
    float* sBuf    = smem + OFF_BUF;
    float* sWd     = sBuf;           // phase-1a alias (4800 <= 6400)
    float* sW1     = sBuf;           // phase-1b alias (5200 <= 6400)

    const int lane = threadIdx.x;    // TPB == 32: tid == lane
    const size_t rowBase = (size_t)blockIdx.x * ROWS_PER_CTA;
    const int rowA = (int)rowBase + lane;         // rows [base+lane, base+32+lane]
    const int rowB = rowA + 32;

    // This CTA's (== warp's) noise tile: 3200 contiguous floats per step.
    const size_t tileOff = rowBase * 50;

    // ---- stage odd Wdrift rows + Wd (into buffer alias) ----
    for (int i = lane; i < 1300; i += TPB) {
        int o = i / 52, k = i - o * 52;
        sWdrOdd[i] = (k < 50) ? Wdrift[(2 * o + 1) * 50 + k] : 0.0f;
    }
    for (int i = lane; i < 4800; i += TPB) {
        int r = i / 96, k = i - r * 96;
        sWd[i] = (k < 90) ? Wd[r * 90 + k] : 0.0f;
    }
    __syncthreads();

    // ================= prologue: out = x @ Wd^T + bd =================
    ull out2A[25], out2B[25];
    prologue_row(x + (size_t)rowA * 90, sWd, out2A);
    prologue_row(x + (size_t)rowB * 90, sWd, out2B);

    __syncthreads();   // done reading Wd; buffer free for W1

    // ---- stage W1 (into buffer alias) ----
    for (int i = lane; i < 5000; i += TPB) {
        int m = i / 50, k = i - m * 50;
        sW1[m * 52 + k] = W1[i];
    }
    __syncthreads();

    // ====== diffusion = 0.5*sigmoid(relu(out@W1^T+b1) @ W2^T + b2) ======
    float daccA = cB2[0], daccB = cB2[0];
#pragma unroll 2
    for (int m = 0; m < 100; ++m) {
        const float* wrow = sW1 + m * 52;
        const ulonglong2* w2r = (const ulonglong2*)wrow;
        ull aA = 0ull, aB = 0ull;
#pragma unroll
        for (int q = 0; q < 12; ++q) {
            ulonglong2 w = w2r[q];
            aA = ffma2(w.x, out2A[2 * q],     aA);
            aA = ffma2(w.y, out2A[2 * q + 1], aA);
            aB = ffma2(w.x, out2B[2 * q],     aB);
            aB = ffma2(w.y, out2B[2 * q + 1], aB);
        }
        ull wt = *(const ull*)(wrow + 48);
        aA = ffma2(wt, out2A[24], aA);
        aB = ffma2(wt, out2B[24], aB);
        float lA, hA, lB, hB;
        unpack2(aA, lA, hA);
        unpack2(aB, lB, hB);
        float bm = cB1[m], w2m = cW2[m];
        daccA = fmaf(w2m, fmaxf(lA + hA + bm, 0.0f), daccA);
        daccB = fmaf(w2m, fmaxf(lB + hB + bm, 0.0f), daccB);
    }
    const float dt   = 4.0f / 20.0f;
    const float sqdt = sqrtf(dt);
    const float diffA = 0.5f / (1.0f + expf(-daccA));
    const float diffB = 0.5f / (1.0f + expf(-daccB));
    const ull dsA = pack2(diffA * sqdt, diffA * sqdt);
    const ull dsB = pack2(diffB * sqdt, diffB * sqdt);
    const ull dt2 = pack2(dt, dt);

    __syncthreads();   // done reading W1; buffer free for noise

    // ---- prefetch noise step0 -> buf0, step1 -> buf1 (coalesced, 2 groups) ----
    {
        const float* n0 = noise + tileOff;
#pragma unroll
        for (int i = 0; i < 25; ++i) {
            int c = lane + 32 * i;
            cp16(sBuf + c * 4, n0 + c * 4);
        }
        asm volatile("cp.async.commit_group;" ::: "memory");
        const float* n1 = noise + (size_t)B_ROWS * 50 + tileOff;
#pragma unroll
        for (int i = 0; i < 25; ++i) {
            int c = lane + 32 * i;
            cp16(sBuf + SLICE + c * 4, n1 + c * 4);
        }
        asm volatile("cp.async.commit_group;" ::: "memory");
    }

    // Constant-space views of even Wdrift rows.
    const ulonglong2* cW16 = (const ulonglong2*)cWdr;
    const ull*        cW8  = (const ull*)cWdr;

    // ================= main SDE loop: double-buffered, warp-scoped =================
#pragma unroll 1
    for (int l = 0; l < L_STEPS; ++l) {
        if (l + 1 < L_STEPS) {
            asm volatile("cp.async.wait_group 1;" ::: "memory");  // step-l group done
        } else {
            asm volatile("cp.async.wait_group 0;" ::: "memory");
        }
        __syncwarp();   // all lanes' step-l copies complete -> tile visible warp-wide

        float* buf = sBuf + (l & 1) * SLICE;
        const ull* nrowA = (const ull*)(buf + lane * 50);
        const ull* nrowB = (const ull*)(buf + 1600 + lane * 50);

        ull dnewA[25], dnewB[25];
#pragma unroll 5
        for (int p = 0; p < 25; ++p) {
            const ulonglong2* w02 = cW16 + 25 * p;            // even row: const port
            const float* w1 = sWdrOdd + p * 52;               // odd row: L1 port
            const ulonglong2* w12 = (const ulonglong2*)w1;
            ull a0A = 0ull, a1A = 0ull, a0B = 0ull, a1B = 0ull;
#pragma unroll
            for (int q = 0; q < 12; ++q) {
                ulonglong2 wa = w02[q];
                a0A = ffma2(wa.x, out2A[2 * q],     a0A);
                a0A = ffma2(wa.y, out2A[2 * q + 1], a0A);
                a0B = ffma2(wa.x, out2B[2 * q],     a0B);
                a0B = ffma2(wa.y, out2B[2 * q + 1], a0B);
                ulonglong2 wb = w12[q];
                a1A = ffma2(wb.x, out2A[2 * q],     a1A);
                a1A = ffma2(wb.y, out2A[2 * q + 1], a1A);
                a1B = ffma2(wb.x, out2B[2 * q],     a1B);
                a1B = ffma2(wb.y, out2B[2 * q + 1], a1B);
            }
            ull wt0 = cW8[50 * p + 24];
            ull wt1 = *(const ull*)(w1 + 48);
            a0A = ffma2(wt0, out2A[24], a0A);
            a1A = ffma2(wt1, out2A[24], a1A);
            a0B = ffma2(wt0, out2B[24], a0B);
            a1B = ffma2(wt1, out2B[24], a1B);

            float l0, h0, l1, h1;
            const float bd0 = cBdr[2 * p], bd1 = cBdr[2 * p + 1];

            unpack2(a0A, l0, h0);
            unpack2(a1A, l1, h1);
            {
                float s0 = fmaxf(l0 + h0 + bd0, 0.0f);
                float s1 = fmaxf(l1 + h1 + bd1, 0.0f);
                ull nv = ffma2(dt2, pack2(s0, s1), out2A[p]);
                dnewA[p] = ffma2(dsA, nrowA[p], nv);
            }
            unpack2(a0B, l0, h0);
            unpack2(a1B, l1, h1);
            {
                float s0 = fmaxf(l0 + h0 + bd0, 0.0f);
                float s1 = fmaxf(l1 + h1 + bd1, 0.0f);
                ull nv = ffma2(dt2, pack2(s0, s1), out2B[p]);
                dnewB[p] = ffma2(dsB, nrowB[p], nv);
            }
        }
#pragma unroll
        for (int p = 0; p < 25; ++p) { out2A[p] = dnewA[p]; out2B[p] = dnewB[p]; }

        __syncwarp();   // all lanes done READING this buffer before refill

        if (l + 2 < L_STEPS) {   // refill the just-drained buffer with noise l+2
            const float* nsrc = noise + (size_t)(l + 2) * B_ROWS * 50 + tileOff;
#pragma unroll
            for (int i = 0; i < 25; ++i) {
                int c = lane + 32 * i;
                cp16(buf + c * 4, nsrc + c * 4);
            }
            asm volatile("cp.async.commit_group;" ::: "memory");
        }
    }

    // ================= epilogue: relu(out) @ Wfc^T + bfc -> (mean, sigma) =================
    const ull* w0 = (const ull*)(cWfc);
    const ull* w1 = (const ull*)(cWfc + 50);
    ull a0A = 0ull, a1A = 0ull, a0B = 0ull, a1B = 0ull;
#pragma unroll
    for (int p = 0; p < 25; ++p) {
        float lo, hi;
        unpack2(out2A[p], lo, hi);
        ull rA = pack2(fmaxf(lo, 0.0f), fmaxf(hi, 0.0f));
        unpack2(out2B[p], lo, hi);
        ull rB = pack2(fmaxf(lo, 0.0f), fmaxf(hi, 0.0f));
        ull wv0 = w0[p], wv1 = w1[p];
        a0A = ffma2(wv0, rA, a0A);
        a1A = ffma2(wv1, rA, a1A);
        a0B = ffma2(wv0, rB, a0B);
        a1B = ffma2(wv1, rB, a1B);
    }
    float m0, m1, z0, z1;
    const float bfc0 = cBfc[0], bfc1 = cBfc[1];

    unpack2(a0A, m0, m1);
    unpack2(a1A, z0, z1);
    {
        const float mean = m0 + m1 + bfc0;
        const float z    = z0 + z1 + bfc1;
        const float sp   = log1pf(expf(-fabsf(z))) + fmaxf(z, 0.0f);
        out[rowA] = mean;
        out[B_ROWS + rowA] = sp + 0.001f;
    }
    unpack2(a0B, m0, m1);
    unpack2(a1B, z0, z1);
    {
        const float mean = m0 + m1 + bfc0;
        const float z    = z0 + z1 + bfc1;
        const float sp   = log1pf(expf(-fabsf(z))) + fmaxf(z, 0.0f);
        out[rowB] = mean;
        out[B_ROWS + rowB] = sp + 0.001f;
    }
}

extern "C" void kernel_launch(void* const* d_in, const int* in_sizes, int n_in,
                              void* d_out, int out_size) {
    (void)in_sizes; (void)n_in; (void)out_size;
    const float* x      = (const float*)d_in[0];
    const float* Wd     = (const float*)d_in[1];
    const float* bd     = (const float*)d_in[2];
    const float* Wdrift = (const float*)d_in[3];
    const float* bdrift = (const float*)d_in[4];
    const float* W1     = (const float*)d_in[5];
    const float* b1     = (const float*)d_in[6];
    const float* W2     = (const float*)d_in[7];
    const float* b2     = (const float*)d_in[8];
    const float* Wfc    = (const float*)d_in[9];
    const float* bfc    = (const float*)d_in[10];
    const float* noise  = (const float*)d_in[11];
    float* out = (float*)d_out;

    // Mirror broadcast operands into constant memory (D2D async, graph-capturable).
    cudaMemcpyToSymbolAsync(cWdr, Wdrift, 2500 * sizeof(float), 0, cudaMemcpyDeviceToDevice);
    cudaMemcpyToSymbolAsync(cBdr, bdrift,   50 * sizeof(float), 0, cudaMemcpyDeviceToDevice);
    cudaMemcpyToSymbolAsync(cBd,  bd,       50 * sizeof(float), 0, cudaMemcpyDeviceToDevice);
    cudaMemcpyToSymbolAsync(cB1,  b1,      100 * sizeof(float), 0, cudaMemcpyDeviceToDevice);
    cudaMemcpyToSymbolAsync(cW2,  W2,      100 * sizeof(float), 0, cudaMemcpyDeviceToDevice);
    cudaMemcpyToSymbolAsync(cWfc, Wfc,     100 * sizeof(float), 0, cudaMemcpyDeviceToDevice);
    cudaMemcpyToSymbolAsync(cB2,  b2,        1 * sizeof(float), 0, cudaMemcpyDeviceToDevice);
    cudaMemcpyToSymbolAsync(cBfc, bfc,       2 * sizeof(float), 0, cudaMemcpyDeviceToDevice);

    cudaFuncSetAttribute(sdenet_kernel,
                         cudaFuncAttributeMaxDynamicSharedMemorySize, SMEM_BYTES);
    sdenet_kernel<<<GRID, TPB, SMEM_BYTES>>>(x, Wd, bd, Wdrift, bdrift,
                                             W1, b1, W2, b2, Wfc, bfc, noise, out);
}

// round 15
// speedup vs baseline: 1.1271x; 1.1271x over previous
#include <cuda_runtime.h>
#include <cstdint>
#include <math.h>

typedef unsigned long long ull;

static constexpr int B_ROWS = 262144;
static constexpr int L_STEPS = 20;
static constexpr int TPB = 64;
static constexpr int ROWS_PER_CTA = 2 * TPB;                 // 128
static constexpr int GRID = B_ROWS / ROWS_PER_CTA;           // 2048

// ---- constant memory: all broadcast operands (const port) ----
__constant__ float cWdr[2500];   // Wdrift [50,50] row-major (even rows read here)
__constant__ float cBdr[50];
__constant__ float cBd[50];
__constant__ float cB1[100];
__constant__ float cW2[100];
__constant__ float cWfc[100];
__constant__ float cB2[1];
__constant__ float cBfc[2];

// ---- shared memory layout (floats) ----
// sWdrOdd [25*52] @ 0     (1300)  odd Wdrift rows, stride 52 (16B-aligned rows)
// sBuf    [6400]  @ 1300  noise tile (128 rows); warp w owns [3200w, 3200w+3200)
//   phase-1 aliases (sequential): sWd[4800] then sW1[5200]
static constexpr int OFF_WDRODD = 0;
static constexpr int OFF_BUF    = 1300;                      // 1300*4=5200, 16B aligned
static constexpr int WARP_SLICE = 3200;                      // floats (64 rows/warp)
static constexpr int SMEM_FLOATS = OFF_BUF + 2 * WARP_SLICE; // 7700
static constexpr int SMEM_BYTES  = SMEM_FLOATS * 4;          // 30800 -> 6 CTAs/SM (reg-capped)

// ---- packed f32x2 helpers (Blackwell 2x-fp32 path; PTX-only) ----
static __device__ __forceinline__ ull ffma2(ull a, ull b, ull c) {
    ull d;
    asm("fma.rn.f32x2 %0, %1, %2, %3;" : "=l"(d) : "l"(a), "l"(b), "l"(c));
    return d;
}
static __device__ __forceinline__ ull pack2(float lo, float hi) {
    ull r;
    asm("mov.b64 %0, {%1, %2};" : "=l"(r) : "f"(lo), "f"(hi));
    return r;
}
static __device__ __forceinline__ void unpack2(ull v, float& lo, float& hi) {
    asm("mov.b64 {%0, %1}, %2;" : "=f"(lo), "=f"(hi) : "l"(v));
}

static __device__ __forceinline__ unsigned smem_u32(const void* p) {
    return (unsigned)__cvta_generic_to_shared(p);
}
static __device__ __forceinline__ void cp16(void* sdst, const void* gsrc) {
    asm volatile("cp.async.cg.shared.global [%0], [%1], 16;"
                 :: "r"(smem_u32(sdst)), "l"(gsrc) : "memory");
}

// Prologue dot for one row, chunked partial sums (bounded register pressure).
static __device__ __forceinline__ void prologue_row(const float* __restrict__ xrow,
                                                    const float* __restrict__ sWd,
                                                    ull* __restrict__ out2) {
#pragma unroll
    for (int p = 0; p < 25; ++p) out2[p] = pack2(cBd[2 * p], cBd[2 * p + 1]);

    for (int c = 0; c < 3; ++c) {
        ull xv[16];
        const ull* xr = (const ull*)xrow + c * 16;
        if (c < 2) {
#pragma unroll
            for (int t = 0; t < 16; ++t) xv[t] = xr[t];
        } else {
#pragma unroll
            for (int t = 0; t < 13; ++t) xv[t] = xr[t];
            xv[13] = 0ull; xv[14] = 0ull; xv[15] = 0ull;   // Wd cols 90..95 are 0
        }
#pragma unroll 5
        for (int p = 0; p < 25; ++p) {
            const ulonglong2* w0 = (const ulonglong2*)(sWd + (2 * p) * 96 + c * 32);
            const ulonglong2* w1 = (const ulonglong2*)(sWd + (2 * p + 1) * 96 + c * 32);
            ull a0 = 0ull, a1 = 0ull;
#pragma unroll
            for (int q = 0; q < 8; ++q) {
                ulonglong2 wa = w0[q];
                a0 = ffma2(wa.x, xv[2 * q],     a0);
                a0 = ffma2(wa.y, xv[2 * q + 1], a0);
                ulonglong2 wb = w1[q];
                a1 = ffma2(wb.x, xv[2 * q],     a1);
                a1 = ffma2(wb.y, xv[2 * q + 1], a1);
            }
            float l0, h0, l1, h1, o0, o1;
            unpack2(a0, l0, h0);
            unpack2(a1, l1, h1);
            unpack2(out2[p], o0, o1);
            out2[p] = pack2(o0 + l0 + h0, o1 + l1 + h1);
        }
    }
}

__global__ void __launch_bounds__(TPB, 6)   // 6 CTAs/SM -> 12 warps/SM, reg cap 170
sdenet_kernel(const float* __restrict__ x,      // [B,90]
              const float* __restrict__ Wd,     // [50,90]
              const float* __restrict__ bd,     // [50]
              const float* __restrict__ Wdrift, // [50,50]
              const float* __restrict__ bdrift, // [50]
              const float* __restrict__ W1,     // [100,50]
              const float* __restrict__ b1,     // [100]
              const float* __restrict__ W2,     // [1,100]
              const float* __restrict__ b2,     // [1]
              const float* __restrict__ Wfc,    // [2,50]
              const float* __restrict__ bfc,    // [2]
              const float* __restrict__ noise,  // [L,B,50]
              float* __restrict__ out)          // [2*B] = mean(B) ++ sigma(B)
{
    extern __shared__ float smem[];
    float* sWdrOdd = smem + OFF_WDRODD;
    float* sBuf    = smem + OFF_BUF;
    float* sWd     = sBuf;           // phase-1a alias (4800 <= 6400)
    float* sW1     = sBuf;           // phase-1b alias (5200 <= 6400)

    const int tid  = threadIdx.x;
    const int warp = tid >> 5;       // 0 or 1
    const int lane = tid & 31;
    const size_t rowBase = (size_t)blockIdx.x * ROWS_PER_CTA;

    // Warp-contiguous row mapping: warp w handles CTA rows [64w, 64w+64).
    const int rowA = (int)rowBase + 64 * warp + lane;
    const int rowB = rowA + 32;

    // Warp-private noise slice (contiguous 12.8 KB in smem and gmem).
    float* wSlice = sBuf + warp * WARP_SLICE;
    const size_t wSliceOff = rowBase * 50 + (size_t)warp * WARP_SLICE;

    // ---- stage odd Wdrift rows + Wd (into buffer alias) ----
    for (int i = tid; i < 1300; i += TPB) {
        int o = i / 52, k = i - o * 52;
        sWdrOdd[i] = (k < 50) ? Wdrift[(2 * o + 1) * 50 + k] : 0.0f;
    }
    for (int i = tid; i < 4800; i += TPB) {
        int r = i / 96, k = i - r * 96;
        sWd[i] = (k < 90) ? Wd[r * 90 + k] : 0.0f;
    }
    __syncthreads();

    // ================= prologue: out = x @ Wd^T + bd =================
    ull out2A[25], out2B[25];
    prologue_row(x + (size_t)rowA * 90, sWd, out2A);
    prologue_row(x + (size_t)rowB * 90, sWd, out2B);

    __syncthreads();   // done reading Wd; buffer free for W1

    // ---- stage W1 (into buffer alias) ----
    for (int i = tid; i < 5000; i += TPB) {
        int m = i / 50, k = i - m * 50;
        sW1[m * 52 + k] = W1[i];
    }
    __syncthreads();

    // ====== diffusion = 0.5*sigmoid(relu(out@W1^T+b1) @ W2^T + b2) ======
    float daccA = cB2[0], daccB = cB2[0];
#pragma unroll 2
    for (int m = 0; m < 100; ++m) {
        const float* wrow = sW1 + m * 52;
        const ulonglong2* w2r = (const ulonglong2*)wrow;
        ull aA = 0ull, aB = 0ull;
#pragma unroll
        for (int q = 0; q < 12; ++q) {
            ulonglong2 w = w2r[q];
            aA = ffma2(w.x, out2A[2 * q],     aA);
            aA = ffma2(w.y, out2A[2 * q + 1], aA);
            aB = ffma2(w.x, out2B[2 * q],     aB);
            aB = ffma2(w.y, out2B[2 * q + 1], aB);
        }
        ull wt = *(const ull*)(wrow + 48);
        aA = ffma2(wt, out2A[24], aA);
        aB = ffma2(wt, out2B[24], aB);
        float lA, hA, lB, hB;
        unpack2(aA, lA, hA);
        unpack2(aB, lB, hB);
        float bm = cB1[m], w2m = cW2[m];
        daccA = fmaf(w2m, fmaxf(lA + hA + bm, 0.0f), daccA);
        daccB = fmaf(w2m, fmaxf(lB + hB + bm, 0.0f), daccB);
    }
    const float dt   = 4.0f / 20.0f;
    const float sqdt = sqrtf(dt);
    const float diffA = 0.5f / (1.0f + expf(-daccA));
    const float diffB = 0.5f / (1.0f + expf(-daccB));
    const ull dsA = pack2(diffA * sqdt, diffA * sqdt);
    const ull dsB = pack2(diffB * sqdt, diffB * sqdt);
    const ull dt2 = pack2(dt, dt);

    __syncthreads();   // done reading W1; buffer free for noise (LAST CTA barrier)

    // ---- per-warp prefetch of step-0 noise slice (coalesced 12.8 KB) ----
    {
        const float* nsrc = noise + wSliceOff;
#pragma unroll
        for (int i = 0; i < 25; ++i) {
            int c = lane + 32 * i;
            cp16(wSlice + c * 4, nsrc + c * 4);
        }
        asm volatile("cp.async.commit_group;" ::: "memory");
    }

    // Constant-space views of even Wdrift rows.
    const ulonglong2* cW16 = (const ulonglong2*)cWdr;
    const ull*        cW8  = (const ull*)cWdr;
    const ull*        cBdr2 = (const ull*)cBdr;

    // ================= main SDE loop: warp-scoped sync only =================
#pragma unroll 1
    for (int l = 0; l < L_STEPS; ++l) {
        asm volatile("cp.async.wait_group 0;" ::: "memory");   // own group done
        __syncwarp();   // slice visible warp-wide

        const ull* nrowA = (const ull*)(wSlice + lane * 50);
        const ull* nrowB = (const ull*)(wSlice + 1600 + lane * 50);

        ull dnewA[25], dnewB[25];
#pragma unroll 5
        for (int p = 0; p < 25; ++p) {
            const ulonglong2* w02 = cW16 + 25 * p;            // even row: const port
            const float* w1 = sWdrOdd + p * 52;               // odd row: L1 port
            const ulonglong2* w12 = (const ulonglong2*)w1;
            ull a0A = 0ull, a1A = 0ull, a0B = 0ull, a1B = 0ull;
#pragma unroll
            for (int q = 0; q < 12; ++q) {
                ulonglong2 wa = w02[q];
                a0A = ffma2(wa.x, out2A[2 * q],     a0A);
                a0A = ffma2(wa.y, out2A[2 * q + 1], a0A);
                a0B = ffma2(wa.x, out2B[2 * q],     a0B);
                a0B = ffma2(wa.y, out2B[2 * q + 1], a0B);
                ulonglong2 wb = w12[q];
                a1A = ffma2(wb.x, out2A[2 * q],     a1A);
                a1A = ffma2(wb.y, out2A[2 * q + 1], a1A);
                a1B = ffma2(wb.x, out2B[2 * q],     a1B);
                a1B = ffma2(wb.y, out2B[2 * q + 1], a1B);
            }
            ull wt0 = cW8[50 * p + 24];
            ull wt1 = *(const ull*)(w1 + 48);
            a0A = ffma2(wt0, out2A[24], a0A);
            a1A = ffma2(wt1, out2A[24], a1A);
            a0B = ffma2(wt0, out2B[24], a0B);
            a1B = ffma2(wt1, out2B[24], a1B);

            float l0, h0, l1, h1, bd0, bd1;
            unpack2(cBdr2[p], bd0, bd1);

            unpack2(a0A, l0, h0);
            unpack2(a1A, l1, h1);
            {
                float s0 = fmaxf(l0 + h0 + bd0, 0.0f);
                float s1 = fmaxf(l1 + h1 + bd1, 0.0f);
                ull nv = ffma2(dt2, pack2(s0, s1), out2A[p]);
                dnewA[p] = ffma2(dsA, nrowA[p], nv);
            }
            unpack2(a0B, l0, h0);
            unpack2(a1B, l1, h1);
            {
                float s0 = fmaxf(l0 + h0 + bd0, 0.0f);
                float s1 = fmaxf(l1 + h1 + bd1, 0.0f);
                ull nv = ffma2(dt2, pack2(s0, s1), out2B[p]);
                dnewB[p] = ffma2(dsB, nrowB[p], nv);
            }
        }
#pragma unroll
        for (int p = 0; p < 25; ++p) { out2A[p] = dnewA[p]; out2B[p] = dnewB[p]; }

        __syncwarp();   // all lanes done READING the slice before overwrite

        if (l + 1 < L_STEPS) {
            const float* nsrc = noise + (size_t)(l + 1) * B_ROWS * 50 + wSliceOff;
#pragma unroll
            for (int i = 0; i < 25; ++i) {
                int c = lane + 32 * i;
                cp16(wSlice + c * 4, nsrc + c * 4);
            }
            asm volatile("cp.async.commit_group;" ::: "memory");
        }
    }

    // ================= epilogue: relu(out) @ Wfc^T + bfc -> (mean, sigma) =================
    const ull* w0 = (const ull*)(cWfc);
    const ull* w1 = (const ull*)(cWfc + 50);
    ull a0A = 0ull, a1A = 0ull, a0B = 0ull, a1B = 0ull;
#pragma unroll
    for (int p = 0; p < 25; ++p) {
        float lo, hi;
        unpack2(out2A[p], lo, hi);
        ull rA = pack2(fmaxf(lo, 0.0f), fmaxf(hi, 0.0f));
        unpack2(out2B[p], lo, hi);
        ull rB = pack2(fmaxf(lo, 0.0f), fmaxf(hi, 0.0f));
        ull wv0 = w0[p], wv1 = w1[p];
        a0A = ffma2(wv0, rA, a0A);
        a1A = ffma2(wv1, rA, a1A);
        a0B = ffma2(wv0, rB, a0B);
        a1B = ffma2(wv1, rB, a1B);
    }
    float m0, m1, z0, z1;
    const float bfc0 = cBfc[0], bfc1 = cBfc[1];

    unpack2(a0A, m0, m1);
    unpack2(a1A, z0, z1);
    {
        const float mean = m0 + m1 + bfc0;
        const float z    = z0 + z1 + bfc1;
        const float sp   = log1pf(expf(-fabsf(z))) + fmaxf(z, 0.0f);
        out[rowA] = mean;
        out[B_ROWS + rowA] = sp + 0.001f;
    }
    unpack2(a0B, m0, m1);
    unpack2(a1B, z0, z1);
    {
        const float mean = m0 + m1 + bfc0;
        const float z    = z0 + z1 + bfc1;
        const float sp   = log1pf(expf(-fabsf(z))) + fmaxf(z, 0.0f);
        out[rowB] = mean;
        out[B_ROWS + rowB] = sp + 0.001f;
    }
}

extern "C" void kernel_launch(void* const* d_in, const int* in_sizes, int n_in,
                              void* d_out, int out_size) {
    (void)in_sizes; (void)n_in; (void)out_size;
    const float* x      = (const float*)d_in[0];
    const float* Wd     = (const float*)d_in[1];
    const float* bd     = (const float*)d_in[2];
    const float* Wdrift = (const float*)d_in[3];
    const float* bdrift = (const float*)d_in[4];
    const float* W1     = (const float*)d_in[5];
    const float* b1     = (const float*)d_in[6];
    const float* W2     = (const float*)d_in[7];
    const float* b2     = (const float*)d_in[8];
    const float* Wfc    = (const float*)d_in[9];
    const float* bfc    = (const float*)d_in[10];
    const float* noise  = (const float*)d_in[11];
    float* out = (float*)d_out;

    cudaMemcpyToSymbolAsync(cWdr, Wdrift, 2500 * sizeof(float), 0, cudaMemcpyDeviceToDevice);
    cudaMemcpyToSymbolAsync(cBdr, bdrift,   50 * sizeof(float), 0, cudaMemcpyDeviceToDevice);
    cudaMemcpyToSymbolAsync(cBd,  bd,       50 * sizeof(float), 0, cudaMemcpyDeviceToDevice);
    cudaMemcpyToSymbolAsync(cB1,  b1,      100 * sizeof(float), 0, cudaMemcpyDeviceToDevice);
    cudaMemcpyToSymbolAsync(cW2,  W2,      100 * sizeof(float), 0, cudaMemcpyDeviceToDevice);
    cudaMemcpyToSymbolAsync(cWfc, Wfc,     100 * sizeof(float), 0, cudaMemcpyDeviceToDevice);
    cudaMemcpyToSymbolAsync(cB2,  b2,        1 * sizeof(float), 0, cudaMemcpyDeviceToDevice);
    cudaMemcpyToSymbolAsync(cBfc, bfc,       2 * sizeof(float), 0, cudaMemcpyDeviceToDevice);

    cudaFuncSetAttribute(sdenet_kernel,
                         cudaFuncAttributeMaxDynamicSharedMemorySize, SMEM_BYTES);
    sdenet_kernel<<<GRID, TPB, SMEM_BYTES>>>(x, Wd, bd, Wdrift, bdrift,
                                             W1, b1, W2, b2, Wfc, bfc, noise, out);
}